// round 9
// baseline (speedup 1.0000x reference)
#include <cuda_runtime.h>
#include <math.h>

// flag: 0=none, 1=pos, 2=neg ; packed flag | (argmax_gt << 2)
#define GMAX 256
#define BMAX 8
#define RSTRIDE 20480
#define CHUNK 128                 // rois per block
#define MAXCH (RSTRIDE / CHUNK)   // 160
#define FULLM 0xffffffffu
#define NTHREADS 512

__device__ unsigned short g_info[BMAX * RSTRIDE];
__device__ int2           g_cnt[BMAX * MAXCH];
__device__ int            g_done = 0;

// ---------------------------------------------------------------------------
// Fused kernel: 4 threads per roi (split-G x4). Each quarter of a warp scans
// a 64-gt slice for the same 8 rois; two shfl_xor merge stages (8, 16) with
// cross-multiplied strict-> compares (low-g side wins ties -> first-max
// preserved exactly). Branchless division-free tournament: ordering by
// prod/(ar+ag) == IoU ordering; one exact __fdiv_rn per roi reproduces
// JAX's rounded quotient. Phase 2 (last finishing block): subsample + emit.
// ---------------------------------------------------------------------------
__global__ void __launch_bounds__(NTHREADS)
fused_kernel(const float4* __restrict__ rois,
             const float4* __restrict__ gts_raw,
             const int* __restrict__ labels,
             float* __restrict__ out,
             int R, int G, int B, int nChunks, int totalBlocks) {
    const int b = blockIdx.y;
    const int tid = threadIdx.x;
    const int wid = tid >> 5, lane = tid & 31;
    const int sub = lane & 7;           // roi slot within warp (8 rois/warp)
    const int quarter = lane >> 3;      // which 64-gt slice this thread scans

    __shared__ float4 sgt[GMAX];     // (tz, tw, tx, ty)
    __shared__ float  sarea[GMAX];
    __shared__ int    sP[16], sN[16];
    __shared__ int    sTicket;
    __shared__ int    posList[BMAX][16];
    __shared__ int    negList[BMAX][64];

    // ---- stage gts ----
    if (tid < GMAX) {
        float4 t = gts_raw[b * G + tid];
        bool valid = (t.x != 0.f) || (t.y != 0.f) || (t.z != 0.f) || (t.w != 0.f);
        const float s = 0.0009765625f;   // 1/1024 exact
        t.x *= s; t.y *= s; t.z *= s; t.w *= s;
        float area = __fmul_rn(fmaxf(__fsub_rn(t.z, t.x), 0.f),
                               fmaxf(__fsub_rn(t.w, t.y), 0.f));
        if (!valid) {
            const float inf = __int_as_float(0x7f800000);
            t = make_float4(inf, inf, inf, inf);  // prod -> NaN, never updates
            area = 0.f;
        }
        sgt[tid] = make_float4(t.z, t.w, t.x, t.y);  // (tz,tw,tx,ty)
        sarea[tid] = area;
    }
    __syncthreads();

    // ---- phase 1: classify (branchless, split-G x4) ----
    const int i = blockIdx.x * CHUNK + wid * 8 + sub;
    float4 r = (i < R) ? rois[b * R + i] : make_float4(0.f, 0.f, 0.f, 0.f);
    bool rvalid = (r.x != 0.f) || (r.y != 0.f) || (r.z != 0.f) || (r.w != 0.f);
    float ar = __fmul_rn(fmaxf(__fsub_rn(r.z, r.x), 0.f),
                         fmaxf(__fsub_rn(r.w, r.y), 0.f));
    const float rx = r.x, ry = r.y, rz = r.z, rw = r.w;

    float bestP = 0.f;   // committed inter (ref-exact on commit)
    float bestS = 1.f;   // committed fl(ar+ag)
    int bi = 0;

    const int g0 = quarter * 64;
    #pragma unroll 8
    for (int j = 0; j < 64; j++) {
        int g = g0 + j;
        float4 t = sgt[g];            // t.x=tz t.y=tw t.z=tx t.w=ty
        float ag = sarea[g];

        float minz = fminf(rz, t.x);
        float minw = fminf(rw, t.y);
        float maxx = fmaxf(rx, t.z);
        float maxy = fmaxf(ry, t.w);
        float ih = fmaxf(__fsub_rn(minz, maxx), 0.f);
        float iw = __fsub_rn(minw, maxy);
        float prod = __fmul_rn(ih, iw);       // == ref inter when it can win
        float s    = __fadd_rn(ar, ag);

        // prod/s ordering == IoU ordering; strict > keeps first-max
        bool upd = __fmul_rn(prod, bestS) > __fmul_rn(bestP, s);
        bestP = upd ? prod : bestP;
        bestS = upd ? s    : bestS;
        bi    = upd ? g    : bi;
    }

    // ---- merge slices: stage xor 8 (q0|q1, q2|q3), then xor 16 ----
    #pragma unroll
    for (int k = 8; k <= 16; k <<= 1) {
        float oP = __shfl_xor_sync(FULLM, bestP, k);
        float oS = __shfl_xor_sync(FULLM, bestS, k);
        int   oB = __shfl_xor_sync(FULLM, bi, k);
        bool amHigh = (lane & k) != 0;    // this thread holds the higher-g slice
        float lP = amHigh ? oP : bestP, lS = amHigh ? oS : bestS;
        int   lB = amHigh ? oB : bi;
        float hP = amHigh ? bestP : oP, hS = amHigh ? bestS : oS;
        int   hB = amHigh ? bi : oB;
        // take high iff strictly greater ratio (low g wins ties -> first-max)
        bool hi = __fmul_rn(hP, lS) > __fmul_rn(lP, hS);
        bestP = hi ? hP : lP;
        bestS = hi ? hS : lS;
        bi    = hi ? hB : lB;
    }

    float uni  = fmaxf(__fsub_rn(bestS, bestP), 1e-7f);
    float best = __fdiv_rn(bestP, uni);       // exact ref rounding

    int fl = 0;
    if (rvalid && quarter == 0) {
        if (best >= 0.5f)      fl = 1;
        else if (best >= 0.1f) fl = 2;
    }
    if (quarter == 0 && i < R)
        g_info[b * RSTRIDE + i] = (unsigned short)(fl | (bi << 2));

    unsigned mP = __ballot_sync(FULLM, fl == 1);   // only lanes 0-7 can be set
    unsigned mN = __ballot_sync(FULLM, fl == 2);
    if (lane == 0) { sP[wid] = __popc(mP); sN[wid] = __popc(mN); }
    __syncthreads();
    if (tid == 0) {
        int p = 0, n = 0;
        #pragma unroll
        for (int w = 0; w < 16; w++) { p += sP[w]; n += sN[w]; }
        g_cnt[b * MAXCH + blockIdx.x] = make_int2(p, n);
    }

    // ---- last-block ticket ----
    __threadfence();
    __syncthreads();
    if (tid == 0) sTicket = atomicAdd(&g_done, 1);
    __syncthreads();
    if (sTicket != totalBlocks - 1) return;
    if (tid == 0) g_done = 0;     // reset for next graph replay
    __threadfence();              // acquire: all blocks' g_info/g_cnt visible

    // ---- phase 2: warp per image (warps 0-7 of 16, B=8) ----
    for (int img = wid; img < B; img += 16) {
        const int imgOff = img * RSTRIDE;

        int carryP = 0, carryN = 0;
        for (int base = 0; base < nChunks; base += 32) {
            if (carryP >= 16 && carryN >= 64) break;
            int c = base + lane;
            int2 cc = (c < nChunks) ? g_cnt[img * MAXCH + c] : make_int2(0, 0);
            int sp = cc.x, sn = cc.y;
            #pragma unroll
            for (int o = 1; o < 32; o <<= 1) {
                int tp = __shfl_up_sync(FULLM, sp, o);
                int tn = __shfl_up_sync(FULLM, sn, o);
                if (lane >= o) { sp += tp; sn += tn; }
            }
            int exP = carryP + sp - cc.x;   // exclusive prefix of chunk c
            int exN = carryN + sn - cc.y;
            bool need = (c < nChunks) &&
                        (((exP < 16) && (cc.x > 0)) || ((exN < 64) && (cc.y > 0)));
            unsigned needMask = __ballot_sync(FULLM, need);
            int totP = __shfl_sync(FULLM, sp, 31);
            int totN = __shfl_sync(FULLM, sn, 31);

            while (needMask) {
                int cl = __ffs(needMask) - 1;
                needMask &= needMask - 1;
                int cidx = base + cl;
                int pr = __shfl_sync(FULLM, exP, cl);
                int nr = __shfl_sync(FULLM, exN, cl);
                int cb2 = cidx * CHUNK;
                int flv[4];
                #pragma unroll
                for (int k = 0; k < 4; k++) {
                    int idx = cb2 + k * 32 + lane;
                    flv[k] = (idx < R) ? (g_info[imgOff + idx] & 3) : 0;
                }
                const unsigned ltm = (1u << lane) - 1u;
                #pragma unroll
                for (int k = 0; k < 4; k++) {
                    unsigned bPm = __ballot_sync(FULLM, flv[k] == 1);
                    unsigned bNm = __ballot_sync(FULLM, flv[k] == 2);
                    if (flv[k] == 1) {
                        int rank = pr + __popc(bPm & ltm);
                        if (rank < 16) posList[img][rank] = cb2 + k * 32 + lane;
                    }
                    if (flv[k] == 2) {
                        int rank = nr + __popc(bNm & ltm);
                        if (rank < 64) negList[img][rank] = cb2 + k * 32 + lane;
                    }
                    pr += __popc(bPm); nr += __popc(bNm);
                }
            }
            carryP += totP; carryN += totN;
        }
        __syncwarp();

        int n_pos = min(carryP, 16);
        int n_neg = min(carryN, 64 - n_pos);

        for (int slot = lane; slot < 64; slot += 32) {
            bool isPos = slot < n_pos;
            bool isNeg = (slot >= n_pos) && (slot < n_pos + n_neg);
            bool valid = isPos || isNeg;
            int ridx = isPos ? posList[img][slot]
                             : (isNeg ? negList[img][slot - n_pos] : 0);

            float roi_o[4] = {0.f, 0.f, 0.f, 0.f};
            float off_o[4] = {0.f, 0.f, 0.f, 0.f};
            int lab = 0;

            if (valid) {
                unsigned short info = g_info[imgOff + ridx];
                int gidx = info >> 2;
                float4 rr = rois[img * R + ridx];
                float4 tt = gts_raw[img * G + gidx];
                const float s = 0.0009765625f;
                tt.x *= s; tt.y *= s; tt.z *= s; tt.w *= s;

                roi_o[0] = rr.x; roi_o[1] = rr.y; roi_o[2] = rr.z; roi_o[3] = rr.w;

                float rh  = fmaxf(rr.z - rr.x, 1e-7f);
                float rw2 = fmaxf(rr.w - rr.y, 1e-7f);
                float rcy = rr.x + 0.5f * rh;
                float rcx = rr.y + 0.5f * rw2;
                float gh  = fmaxf(tt.z - tt.x, 1e-7f);
                float gw  = fmaxf(tt.w - tt.y, 1e-7f);
                float gcy = tt.x + 0.5f * gh;
                float gcx = tt.y + 0.5f * gw;

                off_o[0] = ((gcy - rcy) / rh) / 0.1f;
                off_o[1] = ((gcx - rcx) / rw2) / 0.1f;
                off_o[2] = logf(gh / rh) / 0.2f;
                off_o[3] = logf(gw / rw2) / 0.2f;

                if (isPos) lab = labels[img * G + gidx];
            }

            int slotBase = (img * 64 + slot) * 4;
            float* outOff = out + (size_t)B * 64 * 4;
            float* outLab = out + (size_t)2 * B * 64 * 4;
            #pragma unroll
            for (int k = 0; k < 4; k++) {
                out[slotBase + k]    = roi_o[k];
                outOff[slotBase + k] = off_o[k];
            }
            outLab[img * 64 + slot] = (float)lab;
        }
    }
}

extern "C" void kernel_launch(void* const* d_in, const int* in_sizes, int n_in,
                              void* d_out, int out_size) {
    const float4* rois   = (const float4*)d_in[0];   // (B,R,4) f32
    const float4* gts    = (const float4*)d_in[1];   // (B,G,4) f32 raw pixels
    const int*    labels = (const int*)d_in[2];      // (B,G) i32
    float* out = (float*)d_out;

    const int G = 256;
    int B = in_sizes[2] / G;
    int R = in_sizes[0] / (4 * B);
    int nChunks = (R + CHUNK - 1) / CHUNK;

    dim3 grid(nChunks, B);
    fused_kernel<<<grid, NTHREADS>>>(rois, gts, labels, out, R, G, B, nChunks,
                                     nChunks * B);
}

// round 10
// speedup vs baseline: 1.0429x; 1.0429x over previous
#include <cuda_runtime.h>
#include <math.h>

// flag: 0=none, 1=pos, 2=neg ; packed flag | (argmax_gt << 2)
#define GMAX 256
#define BMAX 8
#define RSTRIDE 20480
#define CHUNK 128                 // rois per block
#define MAXCH (RSTRIDE / CHUNK)   // 160
#define FULLM 0xffffffffu
#define NTHREADS 256

__device__ unsigned short g_info[BMAX * RSTRIDE];
__device__ int2           g_cnt[BMAX * MAXCH];
__device__ int            g_done = 0;

// ---------------------------------------------------------------------------
// Fused kernel: 2 threads per roi (split-G). Lanes 0-15 scan gts [0,128),
// lanes 16-31 scan [128,256); per 4-gt block the tournament is a balanced
// tree of cross-multiplied strict-> compares (higher-g side wins only on
// strict >, so lowest-g-first tie behavior == sequential first-max).
// Ordering by prod/(ar+ag) == IoU ordering exactly; one exact __fdiv_rn per
// roi reproduces JAX's rounded quotient. Invalid gts use a (-1,-1,2,2)/area-0
// sentinel whose prod is never positive, so it can never win a node.
// Phase 2 (last finishing block): warp-per-image subsample + emit.
// ---------------------------------------------------------------------------
__global__ void __launch_bounds__(NTHREADS)
fused_kernel(const float4* __restrict__ rois,
             const float4* __restrict__ gts_raw,
             const int* __restrict__ labels,
             float* __restrict__ out,
             int R, int G, int B, int nChunks, int totalBlocks) {
    const int b = blockIdx.y;
    const int tid = threadIdx.x;
    const int wid = tid >> 5, lane = tid & 31;
    const int sub = lane & 15;          // roi slot within warp
    const int half = lane >> 4;         // which G-half this thread scans

    __shared__ float4 sgt[GMAX];            // (tz, tw, tx, ty)
    __shared__ alignas(16) float sarea[GMAX];
    __shared__ int    sP[8], sN[8];
    __shared__ int    sTicket;
    __shared__ int    posList[BMAX][16];
    __shared__ int    negList[BMAX][64];

    // ---- stage gts ----
    if (tid < GMAX) {
        float4 t = gts_raw[b * G + tid];
        bool valid = (t.x != 0.f) || (t.y != 0.f) || (t.z != 0.f) || (t.w != 0.f);
        const float s = 0.0009765625f;   // 1/1024 exact
        t.x *= s; t.y *= s; t.z *= s; t.w *= s;
        float area = __fmul_rn(fmaxf(__fsub_rn(t.z, t.x), 0.f),
                               fmaxf(__fsub_rn(t.w, t.y), 0.f));
        if (!valid) {
            // sentinel: ih clamps to 0, iw negative -> prod is -0/negative,
            // never strictly beats anything (incl. the (0,1) init)
            t = make_float4(2.f, 2.f, -1.f, -1.f);   // (y1,x1,y2,x2) scrambled
            area = 0.f;
            // below we store (tz,tw,tx,ty) = (-1,-1,2,2)
            sgt[tid] = make_float4(-1.f, -1.f, 2.f, 2.f);
            sarea[tid] = area;
        } else {
            sgt[tid] = make_float4(t.z, t.w, t.x, t.y);  // (tz,tw,tx,ty)
            sarea[tid] = area;
        }
    }
    __syncthreads();

    // ---- phase 1: classify (branchless tree tournament, split-G) ----
    const int i = blockIdx.x * CHUNK + wid * 16 + sub;
    const int iclamp = min(i, R - 1);
    float4 r = rois[b * R + iclamp];
    bool rvalid = (r.x != 0.f) || (r.y != 0.f) || (r.z != 0.f) || (r.w != 0.f);
    float ar = __fmul_rn(fmaxf(__fsub_rn(r.z, r.x), 0.f),
                         fmaxf(__fsub_rn(r.w, r.y), 0.f));
    const float rx = r.x, ry = r.y, rz = r.z, rw = r.w;

    float bestP = 0.f;   // committed inter (ref-exact on commit)
    float bestS = 1.f;   // committed fl(ar+ag)
    int bi = 0;

    const int g0 = half * 128;
    const float4* sareav = reinterpret_cast<const float4*>(sarea);

    #pragma unroll 4
    for (int j = 0; j < 128; j += 4) {
        const int g = g0 + j;
        float4 a4 = sareav[g >> 2];

        float p0, s0, p1, s1, p2, s2, p3, s3;
        {
            float4 t = sgt[g];
            float ih = fmaxf(__fsub_rn(fminf(rz, t.x), fmaxf(rx, t.z)), 0.f);
            float iw = __fsub_rn(fminf(rw, t.y), fmaxf(ry, t.w));
            p0 = __fmul_rn(ih, iw); s0 = __fadd_rn(ar, a4.x);
        }
        {
            float4 t = sgt[g + 1];
            float ih = fmaxf(__fsub_rn(fminf(rz, t.x), fmaxf(rx, t.z)), 0.f);
            float iw = __fsub_rn(fminf(rw, t.y), fmaxf(ry, t.w));
            p1 = __fmul_rn(ih, iw); s1 = __fadd_rn(ar, a4.y);
        }
        {
            float4 t = sgt[g + 2];
            float ih = fmaxf(__fsub_rn(fminf(rz, t.x), fmaxf(rx, t.z)), 0.f);
            float iw = __fsub_rn(fminf(rw, t.y), fmaxf(ry, t.w));
            p2 = __fmul_rn(ih, iw); s2 = __fadd_rn(ar, a4.z);
        }
        {
            float4 t = sgt[g + 3];
            float ih = fmaxf(__fsub_rn(fminf(rz, t.x), fmaxf(rx, t.z)), 0.f);
            float iw = __fsub_rn(fminf(rw, t.y), fmaxf(ry, t.w));
            p3 = __fmul_rn(ih, iw); s3 = __fadd_rn(ar, a4.w);
        }

        // tree: higher-g side wins only on strict > (== sequential first-max)
        bool w01 = __fmul_rn(p1, s0) > __fmul_rn(p0, s1);
        float pA = w01 ? p1 : p0, sA = w01 ? s1 : s0;
        int   gA = w01 ? g + 1 : g;
        bool w23 = __fmul_rn(p3, s2) > __fmul_rn(p2, s3);
        float pB = w23 ? p3 : p2, sB = w23 ? s3 : s2;
        int   gB = w23 ? g + 3 : g + 2;
        bool wAB = __fmul_rn(pB, sA) > __fmul_rn(pA, sB);
        float pW = wAB ? pB : pA, sW = wAB ? sB : sA;
        int   gW = wAB ? gB : gA;
        bool u = __fmul_rn(pW, bestS) > __fmul_rn(bestP, sW);
        bestP = u ? pW : bestP;
        bestS = u ? sW : bestS;
        bi    = u ? gW : bi;
    }

    // ---- merge halves: lanes 0-15 (low g) vs 16-31 (high g) ----
    {
        float oP = __shfl_xor_sync(FULLM, bestP, 16);
        float oS = __shfl_xor_sync(FULLM, bestS, 16);
        int   oB = __shfl_xor_sync(FULLM, bi, 16);
        float lP = half ? oP : bestP, lS = half ? oS : bestS;
        int   lB = half ? oB : bi;
        float hP = half ? bestP : oP, hS = half ? bestS : oS;
        int   hB = half ? bi : oB;
        bool hi = __fmul_rn(hP, lS) > __fmul_rn(lP, hS);
        bestP = hi ? hP : lP;
        bestS = hi ? hS : lS;
        bi    = hi ? hB : lB;
    }

    float uni  = fmaxf(__fsub_rn(bestS, bestP), 1e-7f);
    float best = __fdiv_rn(bestP, uni);       // exact ref rounding

    int fl = 0;
    if (rvalid && half == 0) {
        if (best >= 0.5f)      fl = 1;
        else if (best >= 0.1f) fl = 2;
    }
    if (half == 0 && i < R)
        g_info[b * RSTRIDE + i] = (unsigned short)(fl | (bi << 2));

    unsigned mP = __ballot_sync(FULLM, fl == 1);   // only lanes 0-15 can be set
    unsigned mN = __ballot_sync(FULLM, fl == 2);
    if (lane == 0) { sP[wid] = __popc(mP); sN[wid] = __popc(mN); }
    __syncthreads();
    if (tid == 0) {
        int p = 0, n = 0;
        #pragma unroll
        for (int w = 0; w < 8; w++) { p += sP[w]; n += sN[w]; }
        g_cnt[b * MAXCH + blockIdx.x] = make_int2(p, n);
    }

    // ---- last-block ticket ----
    __threadfence();
    __syncthreads();
    if (tid == 0) sTicket = atomicAdd(&g_done, 1);
    __syncthreads();
    if (sTicket != totalBlocks - 1) return;
    if (tid == 0) g_done = 0;     // reset for next graph replay
    __threadfence();              // acquire: all blocks' g_info/g_cnt visible

    // ---- phase 2: warp per image (8 warps, B=8 -> 1 round) ----
    for (int img = wid; img < B; img += 8) {
        const int imgOff = img * RSTRIDE;

        int carryP = 0, carryN = 0;
        for (int base = 0; base < nChunks; base += 32) {
            if (carryP >= 16 && carryN >= 64) break;
            int c = base + lane;
            int2 cc = (c < nChunks) ? g_cnt[img * MAXCH + c] : make_int2(0, 0);
            int sp = cc.x, sn = cc.y;
            #pragma unroll
            for (int o = 1; o < 32; o <<= 1) {
                int tp = __shfl_up_sync(FULLM, sp, o);
                int tn = __shfl_up_sync(FULLM, sn, o);
                if (lane >= o) { sp += tp; sn += tn; }
            }
            int exP = carryP + sp - cc.x;   // exclusive prefix of chunk c
            int exN = carryN + sn - cc.y;
            bool need = (c < nChunks) &&
                        (((exP < 16) && (cc.x > 0)) || ((exN < 64) && (cc.y > 0)));
            unsigned needMask = __ballot_sync(FULLM, need);
            int totP = __shfl_sync(FULLM, sp, 31);
            int totN = __shfl_sync(FULLM, sn, 31);

            while (needMask) {
                int cl = __ffs(needMask) - 1;
                needMask &= needMask - 1;
                int cidx = base + cl;
                int pr = __shfl_sync(FULLM, exP, cl);
                int nr = __shfl_sync(FULLM, exN, cl);
                int cb2 = cidx * CHUNK;
                int flv[4];
                #pragma unroll
                for (int k = 0; k < 4; k++) {
                    int idx = cb2 + k * 32 + lane;
                    flv[k] = (idx < R) ? (g_info[imgOff + idx] & 3) : 0;
                }
                const unsigned ltm = (1u << lane) - 1u;
                #pragma unroll
                for (int k = 0; k < 4; k++) {
                    unsigned bPm = __ballot_sync(FULLM, flv[k] == 1);
                    unsigned bNm = __ballot_sync(FULLM, flv[k] == 2);
                    if (flv[k] == 1) {
                        int rank = pr + __popc(bPm & ltm);
                        if (rank < 16) posList[img][rank] = cb2 + k * 32 + lane;
                    }
                    if (flv[k] == 2) {
                        int rank = nr + __popc(bNm & ltm);
                        if (rank < 64) negList[img][rank] = cb2 + k * 32 + lane;
                    }
                    pr += __popc(bPm); nr += __popc(bNm);
                }
            }
            carryP += totP; carryN += totN;
        }
        __syncwarp();

        int n_pos = min(carryP, 16);
        int n_neg = min(carryN, 64 - n_pos);

        for (int slot = lane; slot < 64; slot += 32) {
            bool isPos = slot < n_pos;
            bool isNeg = (slot >= n_pos) && (slot < n_pos + n_neg);
            bool valid = isPos || isNeg;
            int ridx = isPos ? posList[img][slot]
                             : (isNeg ? negList[img][slot - n_pos] : 0);

            float roi_o[4] = {0.f, 0.f, 0.f, 0.f};
            float off_o[4] = {0.f, 0.f, 0.f, 0.f};
            int lab = 0;

            if (valid) {
                unsigned short info = g_info[imgOff + ridx];
                int gidx = info >> 2;
                float4 rr = rois[img * R + ridx];
                float4 tt = gts_raw[img * G + gidx];
                const float s = 0.0009765625f;
                tt.x *= s; tt.y *= s; tt.z *= s; tt.w *= s;

                roi_o[0] = rr.x; roi_o[1] = rr.y; roi_o[2] = rr.z; roi_o[3] = rr.w;

                float rh  = fmaxf(rr.z - rr.x, 1e-7f);
                float rw2 = fmaxf(rr.w - rr.y, 1e-7f);
                float rcy = rr.x + 0.5f * rh;
                float rcx = rr.y + 0.5f * rw2;
                float gh  = fmaxf(tt.z - tt.x, 1e-7f);
                float gw  = fmaxf(tt.w - tt.y, 1e-7f);
                float gcy = tt.x + 0.5f * gh;
                float gcx = tt.y + 0.5f * gw;

                off_o[0] = ((gcy - rcy) / rh) / 0.1f;
                off_o[1] = ((gcx - rcx) / rw2) / 0.1f;
                off_o[2] = logf(gh / rh) / 0.2f;
                off_o[3] = logf(gw / rw2) / 0.2f;

                if (isPos) lab = labels[img * G + gidx];
            }

            int slotBase = (img * 64 + slot) * 4;
            float* outOff = out + (size_t)B * 64 * 4;
            float* outLab = out + (size_t)2 * B * 64 * 4;
            #pragma unroll
            for (int k = 0; k < 4; k++) {
                out[slotBase + k]    = roi_o[k];
                outOff[slotBase + k] = off_o[k];
            }
            outLab[img * 64 + slot] = (float)lab;
        }
    }
}

extern "C" void kernel_launch(void* const* d_in, const int* in_sizes, int n_in,
                              void* d_out, int out_size) {
    const float4* rois   = (const float4*)d_in[0];   // (B,R,4) f32
    const float4* gts    = (const float4*)d_in[1];   // (B,G,4) f32 raw pixels
    const int*    labels = (const int*)d_in[2];      // (B,G) i32
    float* out = (float*)d_out;

    const int G = 256;
    int B = in_sizes[2] / G;
    int R = in_sizes[0] / (4 * B);
    int nChunks = (R + CHUNK - 1) / CHUNK;

    dim3 grid(nChunks, B);
    fused_kernel<<<grid, NTHREADS>>>(rois, gts, labels, out, R, G, B, nChunks,
                                     nChunks * B);
}

// round 11
// speedup vs baseline: 1.1704x; 1.1222x over previous
#include <cuda_runtime.h>
#include <math.h>

// flag: 0=none, 1=pos, 2=neg ; packed flag | (argmax_gt << 2)
#define GMAX 256
#define BMAX 8
#define RSTRIDE 20480
#define CHUNK 128                 // rois per block
#define MAXCH (RSTRIDE / CHUNK)   // 160
#define FULLM 0xffffffffu
#define NTHREADS 256

__device__ unsigned short g_info[BMAX * RSTRIDE];
__device__ int2           g_cnt[BMAX * MAXCH];
__device__ int            g_done = 0;

// sat-sub: fl(a-b) clamped to [0,1]; == fmaxf(fl(a-b),0) for coords in [0,1].
__device__ __forceinline__ float subsat(float a, float b) {
    float d;
    asm("sub.rn.sat.f32 %0, %1, %2;" : "=f"(d) : "f"(a), "f"(b));
    return d;
}

// ---------------------------------------------------------------------------
// Fused kernel: 2 threads per roi (split-G). Lanes 0-15 scan gts [0,128),
// lanes 16-31 scan [128,256); merge via shfl_xor(16) with a cross-multiplied
// strict-> compare (low-g side wins ties -> sequential first-max preserved).
// Branchless division-free tournament: ordering by prod/(ar+ag) == IoU
// ordering exactly; one exact __fdiv_rn per roi reproduces JAX's rounded
// quotient. Invalid gts use a (-1,-1,2,2)/area-0 sentinel: prod = -0, never
// wins strict >. ih clamp fused into sub.rn.sat.f32 (fma pipe, not alu).
// Phase 2 (last finishing block): warp-per-image subsample + emit.
// ---------------------------------------------------------------------------
__global__ void __launch_bounds__(NTHREADS)
fused_kernel(const float4* __restrict__ rois,
             const float4* __restrict__ gts_raw,
             const int* __restrict__ labels,
             float* __restrict__ out,
             int R, int G, int B, int nChunks, int totalBlocks) {
    const int b = blockIdx.y;
    const int tid = threadIdx.x;
    const int wid = tid >> 5, lane = tid & 31;
    const int sub = lane & 15;          // roi slot within warp
    const int half = lane >> 4;         // which G-half this thread scans

    __shared__ float4 sgt[GMAX];            // (tz, tw, tx, ty)
    __shared__ alignas(16) float sarea[GMAX];
    __shared__ int    sP[8], sN[8];
    __shared__ int    sTicket;
    __shared__ int    posList[BMAX][16];
    __shared__ int    negList[BMAX][64];

    // ---- stage gts ----
    if (tid < GMAX) {
        float4 t = gts_raw[b * G + tid];
        bool valid = (t.x != 0.f) || (t.y != 0.f) || (t.z != 0.f) || (t.w != 0.f);
        const float s = 0.0009765625f;   // 1/1024 exact
        t.x *= s; t.y *= s; t.z *= s; t.w *= s;
        float area = __fmul_rn(fmaxf(__fsub_rn(t.z, t.x), 0.f),
                               fmaxf(__fsub_rn(t.w, t.y), 0.f));
        if (!valid) {
            // sentinel (tz,tw,tx,ty)=(-1,-1,2,2): ih sat-> 0, prod = -0,
            // never strictly beats anything
            sgt[tid] = make_float4(-1.f, -1.f, 2.f, 2.f);
            sarea[tid] = 0.f;
        } else {
            sgt[tid] = make_float4(t.z, t.w, t.x, t.y);  // (tz,tw,tx,ty)
            sarea[tid] = area;
        }
    }
    __syncthreads();

    // ---- phase 1: classify (branchless running tournament, split-G) ----
    const int i = blockIdx.x * CHUNK + wid * 16 + sub;
    const int iclamp = min(i, R - 1);
    float4 r = rois[b * R + iclamp];
    bool rvalid = (r.x != 0.f) || (r.y != 0.f) || (r.z != 0.f) || (r.w != 0.f);
    float ar = __fmul_rn(fmaxf(__fsub_rn(r.z, r.x), 0.f),
                         fmaxf(__fsub_rn(r.w, r.y), 0.f));
    const float rx = r.x, ry = r.y, rz = r.z, rw = r.w;

    float bestP = 0.f;   // committed inter (ref-exact on commit)
    float bestS = 1.f;   // committed fl(ar+ag)
    int bi = 0;

    const int g0 = half * 128;
    const float4* sareav = reinterpret_cast<const float4*>(sarea);

    #pragma unroll 2
    for (int j = 0; j < 128; j += 4) {
        const int g = g0 + j;
        float4 a4 = sareav[g >> 2];
        float agv[4] = {a4.x, a4.y, a4.z, a4.w};

        #pragma unroll
        for (int k = 0; k < 4; k++) {
            float4 t = sgt[g + k];        // t.x=tz t.y=tw t.z=tx t.w=ty
            float ih = subsat(fminf(rz, t.x), fmaxf(rx, t.z));   // fma pipe
            float iw = __fsub_rn(fminf(rw, t.y), fmaxf(ry, t.w));
            float prod = __fmul_rn(ih, iw);   // == ref inter when it can win
            float s    = __fadd_rn(ar, agv[k]);
            // prod/s ordering == IoU ordering; strict > keeps first-max
            bool upd = __fmul_rn(prod, bestS) > __fmul_rn(bestP, s);
            bestP = upd ? prod : bestP;
            bestS = upd ? s    : bestS;
            bi    = upd ? g + k : bi;
        }
    }

    // ---- merge halves: lanes 0-15 (low g) vs 16-31 (high g) ----
    {
        float oP = __shfl_xor_sync(FULLM, bestP, 16);
        float oS = __shfl_xor_sync(FULLM, bestS, 16);
        int   oB = __shfl_xor_sync(FULLM, bi, 16);
        float lP = half ? oP : bestP, lS = half ? oS : bestS;
        int   lB = half ? oB : bi;
        float hP = half ? bestP : oP, hS = half ? bestS : oS;
        int   hB = half ? bi : oB;
        bool hi = __fmul_rn(hP, lS) > __fmul_rn(lP, hS);
        bestP = hi ? hP : lP;
        bestS = hi ? hS : lS;
        bi    = hi ? hB : lB;
    }

    float uni  = fmaxf(__fsub_rn(bestS, bestP), 1e-7f);
    float best = __fdiv_rn(bestP, uni);       // exact ref rounding

    int fl = 0;
    if (rvalid && half == 0) {
        if (best >= 0.5f)      fl = 1;
        else if (best >= 0.1f) fl = 2;
    }
    if (half == 0 && i < R)
        g_info[b * RSTRIDE + i] = (unsigned short)(fl | (bi << 2));

    unsigned mP = __ballot_sync(FULLM, fl == 1);   // only lanes 0-15 can be set
    unsigned mN = __ballot_sync(FULLM, fl == 2);
    if (lane == 0) { sP[wid] = __popc(mP); sN[wid] = __popc(mN); }
    __syncthreads();
    if (tid == 0) {
        int p = 0, n = 0;
        #pragma unroll
        for (int w = 0; w < 8; w++) { p += sP[w]; n += sN[w]; }
        g_cnt[b * MAXCH + blockIdx.x] = make_int2(p, n);
    }

    // ---- last-block ticket ----
    __threadfence();
    __syncthreads();
    if (tid == 0) sTicket = atomicAdd(&g_done, 1);
    __syncthreads();
    if (sTicket != totalBlocks - 1) return;
    if (tid == 0) g_done = 0;     // reset for next graph replay
    __threadfence();              // acquire: all blocks' g_info/g_cnt visible

    // ---- phase 2: warp per image (8 warps, B=8 -> 1 round) ----
    for (int img = wid; img < B; img += 8) {
        const int imgOff = img * RSTRIDE;

        int carryP = 0, carryN = 0;
        for (int base = 0; base < nChunks; base += 32) {
            if (carryP >= 16 && carryN >= 64) break;
            int c = base + lane;
            int2 cc = (c < nChunks) ? g_cnt[img * MAXCH + c] : make_int2(0, 0);
            int sp = cc.x, sn = cc.y;
            #pragma unroll
            for (int o = 1; o < 32; o <<= 1) {
                int tp = __shfl_up_sync(FULLM, sp, o);
                int tn = __shfl_up_sync(FULLM, sn, o);
                if (lane >= o) { sp += tp; sn += tn; }
            }
            int exP = carryP + sp - cc.x;   // exclusive prefix of chunk c
            int exN = carryN + sn - cc.y;
            bool need = (c < nChunks) &&
                        (((exP < 16) && (cc.x > 0)) || ((exN < 64) && (cc.y > 0)));
            unsigned needMask = __ballot_sync(FULLM, need);
            int totP = __shfl_sync(FULLM, sp, 31);
            int totN = __shfl_sync(FULLM, sn, 31);

            while (needMask) {
                int cl = __ffs(needMask) - 1;
                needMask &= needMask - 1;
                int cidx = base + cl;
                int pr = __shfl_sync(FULLM, exP, cl);
                int nr = __shfl_sync(FULLM, exN, cl);
                int cb2 = cidx * CHUNK;
                int flv[4];
                #pragma unroll
                for (int k = 0; k < 4; k++) {
                    int idx = cb2 + k * 32 + lane;
                    flv[k] = (idx < R) ? (g_info[imgOff + idx] & 3) : 0;
                }
                const unsigned ltm = (1u << lane) - 1u;
                #pragma unroll
                for (int k = 0; k < 4; k++) {
                    unsigned bPm = __ballot_sync(FULLM, flv[k] == 1);
                    unsigned bNm = __ballot_sync(FULLM, flv[k] == 2);
                    if (flv[k] == 1) {
                        int rank = pr + __popc(bPm & ltm);
                        if (rank < 16) posList[img][rank] = cb2 + k * 32 + lane;
                    }
                    if (flv[k] == 2) {
                        int rank = nr + __popc(bNm & ltm);
                        if (rank < 64) negList[img][rank] = cb2 + k * 32 + lane;
                    }
                    pr += __popc(bPm); nr += __popc(bNm);
                }
            }
            carryP += totP; carryN += totN;
        }
        __syncwarp();

        int n_pos = min(carryP, 16);
        int n_neg = min(carryN, 64 - n_pos);

        for (int slot = lane; slot < 64; slot += 32) {
            bool isPos = slot < n_pos;
            bool isNeg = (slot >= n_pos) && (slot < n_pos + n_neg);
            bool valid = isPos || isNeg;
            int ridx = isPos ? posList[img][slot]
                             : (isNeg ? negList[img][slot - n_pos] : 0);

            float roi_o[4] = {0.f, 0.f, 0.f, 0.f};
            float off_o[4] = {0.f, 0.f, 0.f, 0.f};
            int lab = 0;

            if (valid) {
                unsigned short info = g_info[imgOff + ridx];
                int gidx = info >> 2;
                float4 rr = rois[img * R + ridx];
                float4 tt = gts_raw[img * G + gidx];
                const float s = 0.0009765625f;
                tt.x *= s; tt.y *= s; tt.z *= s; tt.w *= s;

                roi_o[0] = rr.x; roi_o[1] = rr.y; roi_o[2] = rr.z; roi_o[3] = rr.w;

                float rh  = fmaxf(rr.z - rr.x, 1e-7f);
                float rw2 = fmaxf(rr.w - rr.y, 1e-7f);
                float rcy = rr.x + 0.5f * rh;
                float rcx = rr.y + 0.5f * rw2;
                float gh  = fmaxf(tt.z - tt.x, 1e-7f);
                float gw  = fmaxf(tt.w - tt.y, 1e-7f);
                float gcy = tt.x + 0.5f * gh;
                float gcx = tt.y + 0.5f * gw;

                off_o[0] = ((gcy - rcy) / rh) / 0.1f;
                off_o[1] = ((gcx - rcx) / rw2) / 0.1f;
                off_o[2] = logf(gh / rh) / 0.2f;
                off_o[3] = logf(gw / rw2) / 0.2f;

                if (isPos) lab = labels[img * G + gidx];
            }

            int slotBase = (img * 64 + slot) * 4;
            float* outOff = out + (size_t)B * 64 * 4;
            float* outLab = out + (size_t)2 * B * 64 * 4;
            #pragma unroll
            for (int k = 0; k < 4; k++) {
                out[slotBase + k]    = roi_o[k];
                outOff[slotBase + k] = off_o[k];
            }
            outLab[img * 64 + slot] = (float)lab;
        }
    }
}

extern "C" void kernel_launch(void* const* d_in, const int* in_sizes, int n_in,
                              void* d_out, int out_size) {
    const float4* rois   = (const float4*)d_in[0];   // (B,R,4) f32
    const float4* gts    = (const float4*)d_in[1];   // (B,G,4) f32 raw pixels
    const int*    labels = (const int*)d_in[2];      // (B,G) i32
    float* out = (float*)d_out;

    const int G = 256;
    int B = in_sizes[2] / G;
    int R = in_sizes[0] / (4 * B);
    int nChunks = (R + CHUNK - 1) / CHUNK;

    dim3 grid(nChunks, B);
    fused_kernel<<<grid, NTHREADS>>>(rois, gts, labels, out, R, G, B, nChunks,
                                     nChunks * B);
}